// round 4
// baseline (speedup 1.0000x reference)
#include <cuda_runtime.h>
#include <cuda_bf16.h>
#include <cstdint>

#define N_PTS   10242
#define C_DIM   64
#define K_DIM   9
#define NBR_DIM 7
#define O_DIM   64
#define BT_DIM  16
#define M_TOTAL (BT_DIM * N_PTS)     /* 163872 */
#define CK_DIM  (C_DIM * K_DIM)      /* 576    */

#define BM      128
#define A_LDB   80                   /* bf16 tile pitch: 64 B row + 16 pad */

// ---------------- SMEM map (dynamic) ---------------------------------------
#define OFF_X    0                   /* [7][128][32] f32             114688 */
#define OFF_T    114688              /* [63][128]   f32               32256 */
#define OFF_IDX  146944              /* [128][7]    i32 (elem offs)    3584 */
#define OFF_N    150528              /* sN[128] i32                     512 */
#define OFF_BB   151040              /* sBB[128] i32 (bt*N_PTS)         512 */
#define OFF_A    151552              /* 2 bufs x (hi 10240 + lo 10240) 40960 */
#define OFF_W    192512              /* 2 bufs x (hi 5120 + lo 5120)  20480 */
#define SMEM_TOT 212992

// ---------------- scratch -----------------------------------------------
__device__ __nv_bfloat16 g_Whi[CK_DIM * O_DIM];  // [o][k*64+c]
__device__ __nv_bfloat16 g_Wlo[CK_DIM * O_DIM];
__device__ int g_is64;

// ---------------- PTX helpers ----------------------------------------------
__device__ __forceinline__ uint32_t smem_u32(const void* p) {
    uint32_t a;
    asm("{ .reg .u64 t; cvta.to.shared.u64 t, %1; cvt.u32.u64 %0, t; }"
        : "=r"(a) : "l"(p));
    return a;
}

#define LDSM_X4(r, addr) \
    asm volatile("ldmatrix.sync.aligned.m8n8.x4.shared.b16 {%0,%1,%2,%3}, [%4];" \
        : "=r"((r)[0]), "=r"((r)[1]), "=r"((r)[2]), "=r"((r)[3]) : "r"(addr))

#define MMA_BF16(d, a, b0, b1) \
    asm volatile("mma.sync.aligned.m16n8k16.row.col.f32.bf16.bf16.f32 " \
        "{%0,%1,%2,%3}, {%4,%5,%6,%7}, {%8,%9}, {%0,%1,%2,%3};" \
        : "+f"((d)[0]), "+f"((d)[1]), "+f"((d)[2]), "+f"((d)[3]) \
        : "r"((a)[0]), "r"((a)[1]), "r"((a)[2]), "r"((a)[3]), "r"(b0), "r"(b1))

// pack two floats -> bf16x2 (c0 in low half, c1 in high half)
__device__ __forceinline__ uint32_t pack_bf2(float c0, float c1) {
    uint32_t r;
    asm("cvt.rn.bf16x2.f32 %0, %1, %2;" : "=r"(r) : "f"(c1), "f"(c0));
    return r;
}

// ---------------- setup kernels ---------------------------------------------
__global__ void detect_idx_kernel(const int* __restrict__ idx32) {
    __shared__ int s_any;
    if (threadIdx.x == 0) s_any = 0;
    __syncthreads();
    int any = 0;
    const int pairs = N_PTS * NBR_DIM / 2;
    for (int i = threadIdx.x; i < pairs; i += blockDim.x)
        any |= (idx32[2 * i + 1] != 0);
    if (any) s_any = 1;
    __syncthreads();
    if (threadIdx.x == 0) g_is64 = (s_any == 0);
}

__global__ void prepack_w_kernel(const float* __restrict__ conv_w) {
    int i = blockIdx.x * 256 + threadIdx.x;
    if (i >= CK_DIM * O_DIM) return;
    int o  = i / CK_DIM;
    int cc = i - o * CK_DIM;
    int k  = cc >> 6;
    int c  = cc & 63;
    float w = conv_w[(o * 64 + c) * 9 + k];
    __nv_bfloat16 hi = __float2bfloat16_rn(w);
    g_Whi[i] = hi;
    g_Wlo[i] = __float2bfloat16_rn(w - __bfloat162float(hi));
}

// ---------------- fused kernel ----------------------------------------------
__global__ void __launch_bounds__(256, 1)
fused_kernel(const float* __restrict__ x,
             const void*  __restrict__ index_raw,
             const float* __restrict__ itp_mat,
             const float* __restrict__ conv_b,
             float* __restrict__ out) {
    extern __shared__ char smem[];
    const uint32_t sb = smem_u32(smem);

    float*    sX   = (float*)(smem + OFF_X);
    float*    sT   = (float*)(smem + OFF_T);
    int*      sIdx = (int*)  (smem + OFF_IDX);
    int*      sN   = (int*)  (smem + OFF_N);
    int*      sBB  = (int*)  (smem + OFF_BB);

    const int tid = threadIdx.x;
    const int wid = tid >> 5;
    const int lid = tid & 31;
    const int wm  = wid & 3;
    const int wn  = wid >> 2;
    const int m0  = blockIdx.x * BM;
    const int is64 = g_is64;

    // ---- setup: per-row n / bt ----
    if (tid < BM) {
        int m = m0 + tid;
        if (m >= M_TOTAL) m = 0;          // safe clamp (results discarded)
        int bt = m / N_PTS;
        int n  = m - bt * N_PTS;
        sN[tid]  = n;
        sBB[tid] = bt * N_PTS;
    }
    __syncthreads();

    // ---- setup: neighbor element offsets + T matrices ----
    for (int i = tid; i < BM * NBR_DIM; i += 256) {
        int row = i / NBR_DIM, j = i - row * NBR_DIM;
        int n = sN[row];
        int v;
        if (is64) v = (int)((const long long*)index_raw)[n * NBR_DIM + j];
        else      v = ((const int*)index_raw)[n * NBR_DIM + j];
        sIdx[i] = (sBB[row] + v) * C_DIM;      // element offset into x (c=0)
    }
    for (int i = tid; i < BM * 63; i += 256) {
        int row = i / 63, e = i - row * 63;    // e = j*9+k
        sT[e * BM + row] = itp_mat[sN[row] * 63 + e];
    }

    // ---- MMA accumulators ----
    float accO[2][4][4];
#pragma unroll
    for (int s = 0; s < 2; s++)
#pragma unroll
        for (int n = 0; n < 4; n++)
#pragma unroll
            for (int q = 0; q < 4; q++) accO[s][n][q] = 0.f;

    // ldmatrix per-lane offsets (relative to tile base)
    const uint32_t aFragOff =
        (uint32_t)((wm * 32 + ((lid >> 3) & 1) * 8 + (lid & 7)) * A_LDB
                   + (lid >> 4) * 16);
    const uint32_t wFragOff =
        (uint32_t)((wn * 32 + (lid >> 4) * 8 + (lid & 7)) * A_LDB
                   + ((lid >> 3) & 1) * 16);

    // interp thread mapping: rows rq*4..+3, channels c4*4..+3 (within half)
    const int rq = tid >> 3;                  // 0..31
    const int c4 = tid & 7;                   // 0..7

    int buf = 0;

    for (int half = 0; half < 2; half++) {
        __syncthreads();                      // protect sX WAR across halves

        // ---- gather x neighbors for this c-half into sX[7][128][32] ----
#pragma unroll
        for (int i = 0; i < 28; i++) {
            int f   = tid + i * 256;          // 0..7167
            int j   = f >> 10;
            int rem = f & 1023;
            int row = rem >> 3;
            int cc4 = rem & 7;
            float4 v = *(const float4*)(x + sIdx[row * NBR_DIM + j]
                                          + half * 32 + cc4 * 4);
            *(float4*)(sX + j * 4096 + row * 32 + cc4 * 4) = v;
        }
        __syncthreads();

        for (int kg = 0; kg < 3; kg++) {
            // ---- prefetch W chunks for this k-group ----
            uint4 wqh[3], wql[3];
#pragma unroll
            for (int kk = 0; kk < 3; kk++) {
                int k = kg * 3 + kk;
                size_t wb = ((size_t)(tid >> 2) * CK_DIM + k * 64
                             + half * 32 + (tid & 3) * 8) * 2;
                wqh[kk] = *(const uint4*)((const char*)g_Whi + wb);
                wql[kk] = *(const uint4*)((const char*)g_Wlo + wb);
            }

            // ---- interp: 3 taps x 4 rows x 4 ch in registers ----
            float acc[3][4][4];
#pragma unroll
            for (int kk = 0; kk < 3; kk++)
#pragma unroll
                for (int ri = 0; ri < 4; ri++)
#pragma unroll
                    for (int ci = 0; ci < 4; ci++) acc[kk][ri][ci] = 0.f;

#pragma unroll
            for (int j = 0; j < NBR_DIM; j++) {
                float4 xv[4];
#pragma unroll
                for (int ri = 0; ri < 4; ri++)
                    xv[ri] = *(const float4*)(sX + j * 4096
                                              + (rq * 4 + ri) * 32 + c4 * 4);
#pragma unroll
                for (int kk = 0; kk < 3; kk++) {
                    int e = j * K_DIM + kg * 3 + kk;
                    float4 tv = *(const float4*)(sT + e * BM + rq * 4);
                    float tr[4] = {tv.x, tv.y, tv.z, tv.w};
#pragma unroll
                    for (int ri = 0; ri < 4; ri++) {
                        acc[kk][ri][0] = fmaf(xv[ri].x, tr[ri], acc[kk][ri][0]);
                        acc[kk][ri][1] = fmaf(xv[ri].y, tr[ri], acc[kk][ri][1]);
                        acc[kk][ri][2] = fmaf(xv[ri].z, tr[ri], acc[kk][ri][2]);
                        acc[kk][ri][3] = fmaf(xv[ri].w, tr[ri], acc[kk][ri][3]);
                    }
                }
            }

            // ---- per tap: split -> STS tiles -> bar -> LDSM+HMMA ----
#pragma unroll
            for (int kk = 0; kk < 3; kk++) {
                char* aHi = smem + OFF_A + buf * 20480;
                char* aLo = aHi + 10240;
                char* wHi = smem + OFF_W + buf * 10240;
                char* wLo = wHi + 5120;

#pragma unroll
                for (int ri = 0; ri < 4; ri++) {
                    float a0 = acc[kk][ri][0], a1 = acc[kk][ri][1];
                    float a2 = acc[kk][ri][2], a3 = acc[kk][ri][3];
                    __nv_bfloat162 h01 = __floats2bfloat162_rn(a0, a1);
                    __nv_bfloat162 h23 = __floats2bfloat162_rn(a2, a3);
                    float2 f01 = __bfloat1622float2(h01);
                    float2 f23 = __bfloat1622float2(h23);
                    uint2 hv, lv;
                    hv.x = *(uint32_t*)&h01;
                    hv.y = *(uint32_t*)&h23;
                    lv.x = pack_bf2(a0 - f01.x, a1 - f01.y);
                    lv.y = pack_bf2(a2 - f23.x, a3 - f23.y);
                    uint32_t ro = (rq * 4 + ri) * A_LDB + c4 * 8;
                    *(uint2*)(aHi + ro) = hv;
                    *(uint2*)(aLo + ro) = lv;
                }
                {
                    uint32_t wo = (tid >> 2) * A_LDB + (tid & 3) * 16;
                    *(uint4*)(wHi + wo) = wqh[kk];
                    *(uint4*)(wLo + wo) = wql[kk];
                }
                __syncthreads();

                const uint32_t uAhi = sb + OFF_A + buf * 20480;
                const uint32_t uAlo = uAhi + 10240;
                const uint32_t uWhi = sb + OFF_W + buf * 10240;
                const uint32_t uWlo = uWhi + 5120;
#pragma unroll
                for (int ks = 0; ks < 2; ks++) {
                    const uint32_t kB = ks * 32;
                    uint32_t ah[2][4], al[2][4], wh[2][4], wl[2][4];
#pragma unroll
                    for (int s = 0; s < 2; s++) {
                        LDSM_X4(ah[s], uAhi + aFragOff + s * 16 * A_LDB + kB);
                        LDSM_X4(al[s], uAlo + aFragOff + s * 16 * A_LDB + kB);
                    }
#pragma unroll
                    for (int g = 0; g < 2; g++) {
                        LDSM_X4(wh[g], uWhi + wFragOff + g * 16 * A_LDB + kB);
                        LDSM_X4(wl[g], uWlo + wFragOff + g * 16 * A_LDB + kB);
                    }
#pragma unroll
                    for (int s = 0; s < 2; s++)
#pragma unroll
                        for (int g = 0; g < 2; g++) {
                            MMA_BF16(accO[s][g * 2 + 0], ah[s], wh[g][0], wh[g][1]);
                            MMA_BF16(accO[s][g * 2 + 1], ah[s], wh[g][2], wh[g][3]);
                            MMA_BF16(accO[s][g * 2 + 0], al[s], wh[g][0], wh[g][1]);
                            MMA_BF16(accO[s][g * 2 + 1], al[s], wh[g][2], wh[g][3]);
                            MMA_BF16(accO[s][g * 2 + 0], ah[s], wl[g][0], wl[g][1]);
                            MMA_BF16(accO[s][g * 2 + 1], ah[s], wl[g][2], wl[g][3]);
                        }
                }
                buf ^= 1;
            }
        }
    }

    // ---- epilogue: bias + store ----
    float bias[4][2];
#pragma unroll
    for (int n = 0; n < 4; n++) {
        int ob = wn * 32 + n * 8 + (lid & 3) * 2;
        bias[n][0] = __ldg(conv_b + ob);
        bias[n][1] = __ldg(conv_b + ob + 1);
    }
#pragma unroll
    for (int s = 0; s < 2; s++)
#pragma unroll
        for (int h = 0; h < 2; h++) {
            int m = m0 + wm * 32 + s * 16 + h * 8 + (lid >> 2);
            if (m < M_TOTAL) {
                float* op = out + (size_t)m * O_DIM + wn * 32 + (lid & 3) * 2;
#pragma unroll
                for (int n = 0; n < 4; n++) {
                    float2 v;
                    v.x = accO[s][n][h * 2 + 0] + bias[n][0];
                    v.y = accO[s][n][h * 2 + 1] + bias[n][1];
                    *(float2*)(op + n * 8) = v;
                }
            }
        }
}

// ---------------------------------------------------------------------------
extern "C" void kernel_launch(void* const* d_in, const int* in_sizes, int n_in,
                              void* d_out, int out_size) {
    const float* x       = (const float*)d_in[0];
    const void*  index   = d_in[1];
    const float* itp_mat = (const float*)d_in[2];
    const float* conv_w  = (const float*)d_in[3];
    const float* conv_b  = (const float*)d_in[4];
    float*       out     = (float*)d_out;

    detect_idx_kernel<<<1, 256>>>((const int*)index);
    prepack_w_kernel<<<(CK_DIM * O_DIM + 255) / 256, 256>>>(conv_w);

    cudaFuncSetAttribute(fused_kernel,
                         cudaFuncAttributeMaxDynamicSharedMemorySize, SMEM_TOT);
    fused_kernel<<<(M_TOTAL + BM - 1) / BM, 256, SMEM_TOT>>>(
        x, index, itp_mat, conv_b, out);
}

// round 6
// speedup vs baseline: 2.2259x; 2.2259x over previous
#include <cuda_runtime.h>
#include <cuda_fp16.h>
#include <cstdint>

#define N_PTS   10242
#define C_DIM   64
#define K_DIM   9
#define NBR_DIM 7
#define O_DIM   64
#define BT_DIM  16
#define M_TOTAL (BT_DIM * N_PTS)     /* 163872 */
#define CK_DIM  (C_DIM * K_DIM)      /* 576    */

#define BM       128
#define BK       32
#define N_CHUNKS (CK_DIM / BK)       /* 18 */
#define A_LDB    80                  /* smem row pitch bytes: 64 B + 16 pad */

// ---------------- scratch ----------------------------------------------------
__device__ __half g_A  [(size_t)M_TOTAL * CK_DIM];   // A fp16, [m][k*64+c]
__device__ __half g_Whi[CK_DIM * O_DIM];             // W hi fp16, [o][k*64+c]
__device__ __half g_Wlo[CK_DIM * O_DIM];             // W lo fp16
__device__ int    g_any;                             // any nonzero high word

// ---------------- PTX helpers ------------------------------------------------
__device__ __forceinline__ uint32_t smem_u32(const void* p) {
    uint32_t a;
    asm("{ .reg .u64 t; cvta.to.shared.u64 t, %1; cvt.u32.u64 %0, t; }"
        : "=r"(a) : "l"(p));
    return a;
}

#define LDSM_X4(r, addr) \
    asm volatile("ldmatrix.sync.aligned.m8n8.x4.shared.b16 {%0,%1,%2,%3}, [%4];" \
        : "=r"((r)[0]), "=r"((r)[1]), "=r"((r)[2]), "=r"((r)[3]) : "r"(addr))

#define MMA_F16(d, a, b0, b1) \
    asm volatile("mma.sync.aligned.m16n8k16.row.col.f32.f16.f16.f32 " \
        "{%0,%1,%2,%3}, {%4,%5,%6,%7}, {%8,%9}, {%0,%1,%2,%3};" \
        : "+f"((d)[0]), "+f"((d)[1]), "+f"((d)[2]), "+f"((d)[3]) \
        : "r"((a)[0]), "r"((a)[1]), "r"((a)[2]), "r"((a)[3]), "r"(b0), "r"(b1))

// ---------------- setup kernels ----------------------------------------------
// prepack also resets g_any (runs before detect in stream order)
__global__ void prepack_w_kernel(const float* __restrict__ conv_w) {
    if (blockIdx.x == 0 && threadIdx.x == 0) g_any = 0;
    int i = blockIdx.x * 256 + threadIdx.x;
    if (i >= CK_DIM * O_DIM) return;
    int o  = i / CK_DIM;
    int cc = i - o * CK_DIM;
    int k  = cc >> 6;
    int c  = cc & 63;
    float w = conv_w[(o * 64 + c) * 9 + k];
    __half hi = __float2half_rn(w);
    g_Whi[i] = hi;
    g_Wlo[i] = __float2half_rn(w - __half2float(hi));
}

__global__ void detect_idx_kernel(const int* __restrict__ idx32) {
    int any = 0;
    const int pairs = N_PTS * NBR_DIM / 2;
    for (int i = blockIdx.x * 256 + threadIdx.x; i < pairs; i += gridDim.x * 256)
        any |= (idx32[2 * i + 1] != 0);
    any = __syncthreads_or(any);
    if (threadIdx.x == 0 && any) atomicOr(&g_any, 1);
}

// ---------------- phase 1: interpolation -> fp16 A ---------------------------
// Block: 256 thr = 8 rows x 32 lanes; lane handles channels 2L, 2L+1.
__global__ void interp_kernel(const float* __restrict__ x,
                              const void*  __restrict__ index_raw,
                              const float* __restrict__ itp_mat) {
    __shared__ float sT[8][NBR_DIM * K_DIM];
    __shared__ int   sIdx[8][NBR_DIM];
    const int tid = threadIdx.x;
    const int m0  = blockIdx.x * 8;
    const int is64 = (g_any == 0);

    for (int i = tid; i < 8 * 63; i += 256) {
        int mi = i / 63, e = i - mi * 63;
        int n = (m0 + mi) % N_PTS;
        sT[mi][e] = itp_mat[n * 63 + e];
    }
    if (tid < 8 * NBR_DIM) {
        int mi = tid / NBR_DIM, j = tid - mi * NBR_DIM;
        int n = (m0 + mi) % N_PTS;
        int v;
        if (is64) v = (int)((const long long*)index_raw)[n * NBR_DIM + j];
        else      v = ((const int*)index_raw)[n * NBR_DIM + j];
        sIdx[mi][j] = v;
    }
    __syncthreads();

    const int lane = tid & 31;
    const int mloc = tid >> 5;
    const int c0   = lane * 2;
    const int m    = m0 + mloc;                 // grid exact
    const int bt   = m / N_PTS;
    const float* xb = x + (size_t)bt * N_PTS * C_DIM;

    float a0[K_DIM], a1[K_DIM];
#pragma unroll
    for (int k = 0; k < K_DIM; k++) { a0[k] = 0.f; a1[k] = 0.f; }

#pragma unroll
    for (int j = 0; j < NBR_DIM; j++) {
        float2 v = *(const float2*)(xb + (size_t)sIdx[mloc][j] * C_DIM + c0);
        const float* tj = &sT[mloc][j * K_DIM];
#pragma unroll
        for (int k = 0; k < K_DIM; k++) {
            a0[k] = fmaf(v.x, tj[k], a0[k]);
            a1[k] = fmaf(v.y, tj[k], a1[k]);
        }
    }

    __half* dst = g_A + (size_t)m * CK_DIM + c0;
#pragma unroll
    for (int k = 0; k < K_DIM; k++)
        *(__half2*)(dst + k * 64) = __floats2half2_rn(a0[k], a1[k]);
}

// ---------------- phase 2: HMMA fp16 GEMM (A single, W hi/lo) ---------------
__global__ void __launch_bounds__(256, 2)
gemm_mma_kernel(const float* __restrict__ conv_b, float* __restrict__ out) {
    __shared__ uint8_t sA  [BM * A_LDB];        // 10 KB
    __shared__ uint8_t sWhi[O_DIM * A_LDB];     //  5 KB
    __shared__ uint8_t sWlo[O_DIM * A_LDB];     //  5 KB

    const int tid = threadIdx.x;
    const int wid = tid >> 5;
    const int lid = tid & 31;
    const int wm  = wid & 3;
    const int wn  = wid >> 2;
    const int m0  = blockIdx.x * BM;

    const uint32_t aFragOff =
        (uint32_t)((wm * 32 + ((lid >> 3) & 1) * 8 + (lid & 7)) * A_LDB
                   + (lid >> 4) * 16);
    const uint32_t wFragOff =
        (uint32_t)((wn * 32 + (lid >> 4) * 8 + (lid & 7)) * A_LDB
                   + ((lid >> 3) & 1) * 16);

    const uint32_t uA   = smem_u32(sA);
    const uint32_t uWhi = smem_u32(sWhi);
    const uint32_t uWlo = smem_u32(sWlo);

    float acc[2][4][4];
#pragma unroll
    for (int s = 0; s < 2; s++)
#pragma unroll
        for (int n = 0; n < 4; n++)
#pragma unroll
            for (int q = 0; q < 4; q++) acc[s][n][q] = 0.f;

    // gmem indexing: A tile = 128 rows x 64 B = 512 x 16B units (2/thread);
    // W tiles = 64 x 64 B = 256 units (1/thread each).
    const int aRow0 = tid >> 2;            // 0..63  (+64 for second unit)
    const int aU    = tid & 3;
    const char* pA   = (const char*)g_A;
    const char* pWhi = (const char*)g_Whi;
    const char* pWlo = (const char*)g_Wlo;

    uint4 rA[2], rWh, rWl;
    const uint4 Z4 = make_uint4(0, 0, 0, 0);

    // prefetch chunk 0
    {
#pragma unroll
        for (int i = 0; i < 2; i++) {
            int m = m0 + aRow0 + i * 64;
            size_t off = (size_t)m * (CK_DIM * 2) + aU * 16;
            rA[i] = (m < M_TOTAL) ? *(const uint4*)(pA + off) : Z4;
        }
        size_t woff = (size_t)(tid >> 2) * (CK_DIM * 2) + aU * 16;
        rWh = *(const uint4*)(pWhi + woff);
        rWl = *(const uint4*)(pWlo + woff);
    }

    for (int ch = 0; ch < N_CHUNKS; ch++) {
        __syncthreads();
#pragma unroll
        for (int i = 0; i < 2; i++)
            *(uint4*)(sA + (aRow0 + i * 64) * A_LDB + aU * 16) = rA[i];
        *(uint4*)(sWhi + (tid >> 2) * A_LDB + aU * 16) = rWh;
        *(uint4*)(sWlo + (tid >> 2) * A_LDB + aU * 16) = rWl;
        __syncthreads();

        if (ch + 1 < N_CHUNKS) {
            const int ccB = (ch + 1) * BK * 2;
#pragma unroll
            for (int i = 0; i < 2; i++) {
                int m = m0 + aRow0 + i * 64;
                size_t off = (size_t)m * (CK_DIM * 2) + ccB + aU * 16;
                rA[i] = (m < M_TOTAL) ? *(const uint4*)(pA + off) : Z4;
            }
            size_t woff = (size_t)(tid >> 2) * (CK_DIM * 2) + ccB + aU * 16;
            rWh = *(const uint4*)(pWhi + woff);
            rWl = *(const uint4*)(pWlo + woff);
        }

#pragma unroll
        for (int ks = 0; ks < 2; ks++) {
            const uint32_t kB = ks * 32;
            uint32_t af[2][4], wh[2][4], wl[2][4];
#pragma unroll
            for (int s = 0; s < 2; s++)
                LDSM_X4(af[s], uA + aFragOff + s * 16 * A_LDB + kB);
#pragma unroll
            for (int g = 0; g < 2; g++) {
                LDSM_X4(wh[g], uWhi + wFragOff + g * 16 * A_LDB + kB);
                LDSM_X4(wl[g], uWlo + wFragOff + g * 16 * A_LDB + kB);
            }
#pragma unroll
            for (int s = 0; s < 2; s++)
#pragma unroll
                for (int g = 0; g < 2; g++) {
                    MMA_F16(acc[s][g * 2 + 0], af[s], wh[g][0], wh[g][1]);
                    MMA_F16(acc[s][g * 2 + 1], af[s], wh[g][2], wh[g][3]);
                    MMA_F16(acc[s][g * 2 + 0], af[s], wl[g][0], wl[g][1]);
                    MMA_F16(acc[s][g * 2 + 1], af[s], wl[g][2], wl[g][3]);
                }
        }
    }

    // ---- epilogue ----
    float bias[4][2];
#pragma unroll
    for (int n = 0; n < 4; n++) {
        int ob = wn * 32 + n * 8 + (lid & 3) * 2;
        bias[n][0] = __ldg(conv_b + ob);
        bias[n][1] = __ldg(conv_b + ob + 1);
    }
#pragma unroll
    for (int s = 0; s < 2; s++)
#pragma unroll
        for (int h = 0; h < 2; h++) {
            int m = m0 + wm * 32 + s * 16 + h * 8 + (lid >> 2);
            if (m < M_TOTAL) {
                float* op = out + (size_t)m * O_DIM + wn * 32 + (lid & 3) * 2;
#pragma unroll
                for (int n = 0; n < 4; n++) {
                    float2 v;
                    v.x = acc[s][n][h * 2 + 0] + bias[n][0];
                    v.y = acc[s][n][h * 2 + 1] + bias[n][1];
                    *(float2*)(op + n * 8) = v;
                }
            }
        }
}

// ---------------------------------------------------------------------------
extern "C" void kernel_launch(void* const* d_in, const int* in_sizes, int n_in,
                              void* d_out, int out_size) {
    const float* x       = (const float*)d_in[0];
    const void*  index   = d_in[1];
    const float* itp_mat = (const float*)d_in[2];
    const float* conv_w  = (const float*)d_in[3];
    const float* conv_b  = (const float*)d_in[4];
    float*       out     = (float*)d_out;

    prepack_w_kernel<<<(CK_DIM * O_DIM + 255) / 256, 256>>>(conv_w);
    detect_idx_kernel<<<64, 256>>>((const int*)index);
    interp_kernel<<<M_TOTAL / 8, 256>>>(x, index, itp_mat);
    gemm_mma_kernel<<<(M_TOTAL + BM - 1) / BM, 256>>>(conv_b, out);
}

// round 7
// speedup vs baseline: 2.5583x; 1.1493x over previous
#include <cuda_runtime.h>
#include <cuda_fp16.h>
#include <cstdint>

#define N_PTS   10242
#define C_DIM   64
#define K_DIM   9
#define NBR_DIM 7
#define O_DIM   64
#define BT_DIM  16
#define M_TOTAL (BT_DIM * N_PTS)     /* 163872 */
#define CK_DIM  (C_DIM * K_DIM)      /* 576    */

#define BM       128
#define BK       32
#define N_CHUNKS (CK_DIM / BK)       /* 18 */
#define A_LDB    80                  /* smem row pitch bytes: 64 B + 16 pad */

// ---------------- scratch ----------------------------------------------------
__device__ __half g_A[(size_t)M_TOTAL * CK_DIM];     // A fp16, [m][k*64+c]
// W in MMA B-fragment layout: [wn][ch][ks][g] -> 32 lanes x uint4 (512 B each)
__device__ uint4  g_Wfrag[2 * N_CHUNKS * 2 * 2 * 32];
__device__ int    g_any;

// ---------------- PTX helpers ------------------------------------------------
__device__ __forceinline__ uint32_t smem_u32(const void* p) {
    uint32_t a;
    asm("{ .reg .u64 t; cvta.to.shared.u64 t, %1; cvt.u32.u64 %0, t; }"
        : "=r"(a) : "l"(p));
    return a;
}

#define LDSM_X4(r, addr) \
    asm volatile("ldmatrix.sync.aligned.m8n8.x4.shared.b16 {%0,%1,%2,%3}, [%4];" \
        : "=r"((r)[0]), "=r"((r)[1]), "=r"((r)[2]), "=r"((r)[3]) : "r"(addr))

#define MMA_F16(d, a, b0, b1) \
    asm volatile("mma.sync.aligned.m16n8k16.row.col.f32.f16.f16.f32 " \
        "{%0,%1,%2,%3}, {%4,%5,%6,%7}, {%8,%9}, {%0,%1,%2,%3};" \
        : "+f"((d)[0]), "+f"((d)[1]), "+f"((d)[2]), "+f"((d)[3]) \
        : "r"((a)[0]), "r"((a)[1]), "r"((a)[2]), "r"((a)[3]), "r"(b0), "r"(b1))

// ---------------- setup kernels ----------------------------------------------
// Build W fragments. For (wn, ch, ks, g), lane l, reg j:
//   o  = wn*32 + g*16 + (j>>1)*8 + (l>>2)
//   kg = ch*32 + ks*16 + (j&1)*8 + (l&3)*2 + {0,1}
//   W(o,kg) = conv_w[(o*64 + (kg&63))*9 + (kg>>6)]
__global__ void prepack_wfrag_kernel(const float* __restrict__ conv_w) {
    if (blockIdx.x == 0 && threadIdx.x == 0) g_any = 0;
    int u = blockIdx.x * 256 + threadIdx.x;        // uint32 index
    const int TOT = 2 * N_CHUNKS * 2 * 2 * 32 * 4; // 36864
    if (u >= TOT) return;
    int j    = u & 3;
    int lane = (u >> 2) & 31;
    int g    = (u >> 7) & 1;
    int ks   = (u >> 8) & 1;
    int ch   = (u >> 9) % N_CHUNKS;
    int wn   = u / (N_CHUNKS * 512);

    int o  = wn * 32 + g * 16 + (j >> 1) * 8 + (lane >> 2);
    int kg = ch * 32 + ks * 16 + (j & 1) * 8 + (lane & 3) * 2;

    float w0 = conv_w[(o * 64 + (kg & 63)) * 9 + (kg >> 6)];
    float w1 = conv_w[(o * 64 + ((kg + 1) & 63)) * 9 + ((kg + 1) >> 6)];
    __half h0 = __float2half_rn(w0);
    __half h1 = __float2half_rn(w1);
    uint32_t packed = ((uint32_t)*(uint16_t*)&h1 << 16) | *(uint16_t*)&h0;
    ((uint32_t*)g_Wfrag)[u] = packed;
}

__global__ void detect_idx_kernel(const int* __restrict__ idx32) {
    int any = 0;
    const int pairs = N_PTS * NBR_DIM / 2;
    for (int i = blockIdx.x * 256 + threadIdx.x; i < pairs; i += gridDim.x * 256)
        any |= (idx32[2 * i + 1] != 0);
    any = __syncthreads_or(any);
    if (threadIdx.x == 0 && any) atomicOr(&g_any, 1);
}

// ---------------- phase 1: interpolation -> fp16 A ---------------------------
__global__ void interp_kernel(const float* __restrict__ x,
                              const void*  __restrict__ index_raw,
                              const float* __restrict__ itp_mat) {
    __shared__ float sT[8][NBR_DIM * K_DIM];
    __shared__ int   sIdx[8][NBR_DIM];
    const int tid = threadIdx.x;
    const int m0  = blockIdx.x * 8;
    const int is64 = (g_any == 0);

    for (int i = tid; i < 8 * 63; i += 256) {
        int mi = i / 63, e = i - mi * 63;
        int n = (m0 + mi) % N_PTS;
        sT[mi][e] = itp_mat[n * 63 + e];
    }
    if (tid < 8 * NBR_DIM) {
        int mi = tid / NBR_DIM, j = tid - mi * NBR_DIM;
        int n = (m0 + mi) % N_PTS;
        int v;
        if (is64) v = (int)((const long long*)index_raw)[n * NBR_DIM + j];
        else      v = ((const int*)index_raw)[n * NBR_DIM + j];
        sIdx[mi][j] = v;
    }
    __syncthreads();

    const int lane = tid & 31;
    const int mloc = tid >> 5;
    const int c0   = lane * 2;
    const int m    = m0 + mloc;
    const int bt   = m / N_PTS;
    const float* xb = x + (size_t)bt * N_PTS * C_DIM;

    float a0[K_DIM], a1[K_DIM];
#pragma unroll
    for (int k = 0; k < K_DIM; k++) { a0[k] = 0.f; a1[k] = 0.f; }

#pragma unroll
    for (int j = 0; j < NBR_DIM; j++) {
        float2 v = *(const float2*)(xb + (size_t)sIdx[mloc][j] * C_DIM + c0);
        const float* tj = &sT[mloc][j * K_DIM];
#pragma unroll
        for (int k = 0; k < K_DIM; k++) {
            a0[k] = fmaf(v.x, tj[k], a0[k]);
            a1[k] = fmaf(v.y, tj[k], a1[k]);
        }
    }

    __half* dst = g_A + (size_t)m * CK_DIM + c0;
#pragma unroll
    for (int k = 0; k < K_DIM; k++) {
        __half2 h = __floats2half2_rn(a0[k], a1[k]);
        __stcs((unsigned int*)(dst + k * 64), *(unsigned int*)&h);  // streaming
    }
}

// ---------------- phase 2: HMMA fp16 GEMM (A smem, W frag-LDG) ---------------
__global__ void __launch_bounds__(256, 2)
gemm_mma_kernel(const float* __restrict__ conv_b, float* __restrict__ out) {
    __shared__ uint8_t sA[BM * A_LDB];          // 10 KB

    const int tid = threadIdx.x;
    const int wid = tid >> 5;
    const int lid = tid & 31;
    const int wm  = wid & 3;
    const int wn  = wid >> 2;
    const int m0  = blockIdx.x * BM;

    const uint32_t aFragOff =
        (uint32_t)((wm * 32 + ((lid >> 3) & 1) * 8 + (lid & 7)) * A_LDB
                   + (lid >> 4) * 16);
    const uint32_t uA = smem_u32(sA);

    float acc[2][4][4];
#pragma unroll
    for (int s = 0; s < 2; s++)
#pragma unroll
        for (int n = 0; n < 4; n++)
#pragma unroll
            for (int q = 0; q < 4; q++) acc[s][n][q] = 0.f;

    // A gmem indexing: 128 rows x 64 B = 512 x 16B units, 2 per thread
    const int aRow0 = tid >> 2;
    const int aU    = tid & 3;
    const char* pA = (const char*)g_A;

    // W fragment base for this warp's wn group (q = ks*2 + g)
    const uint4* pW = g_Wfrag + (size_t)(wn * N_CHUNKS) * 4 * 32 + lid;

    uint4 rA[2], wcur[4], wnxt[4];
    const uint4 Z4 = make_uint4(0, 0, 0, 0);

    // prefetch chunk 0
#pragma unroll
    for (int i = 0; i < 2; i++) {
        int m = m0 + aRow0 + i * 64;
        size_t off = (size_t)m * (CK_DIM * 2) + aU * 16;
        rA[i] = (m < M_TOTAL) ? __ldcs((const uint4*)(pA + off)) : Z4;
    }
#pragma unroll
    for (int q = 0; q < 4; q++) wcur[q] = __ldg(pW + q * 32);

    for (int ch = 0; ch < N_CHUNKS; ch++) {
        __syncthreads();
#pragma unroll
        for (int i = 0; i < 2; i++)
            *(uint4*)(sA + (aRow0 + i * 64) * A_LDB + aU * 16) = rA[i];
        __syncthreads();

        if (ch + 1 < N_CHUNKS) {
            const int ccB = (ch + 1) * BK * 2;
#pragma unroll
            for (int i = 0; i < 2; i++) {
                int m = m0 + aRow0 + i * 64;
                size_t off = (size_t)m * (CK_DIM * 2) + ccB + aU * 16;
                rA[i] = (m < M_TOTAL) ? __ldcs((const uint4*)(pA + off)) : Z4;
            }
#pragma unroll
            for (int q = 0; q < 4; q++)
                wnxt[q] = __ldg(pW + ((ch + 1) * 4 + q) * 32);
        }

#pragma unroll
        for (int ks = 0; ks < 2; ks++) {
            const uint32_t kB = ks * 32;
            uint32_t af[2][4];
#pragma unroll
            for (int s = 0; s < 2; s++)
                LDSM_X4(af[s], uA + aFragOff + s * 16 * A_LDB + kB);
#pragma unroll
            for (int s = 0; s < 2; s++)
#pragma unroll
                for (int g = 0; g < 2; g++) {
                    const uint4 w = wcur[ks * 2 + g];
                    MMA_F16(acc[s][g * 2 + 0], af[s], w.x, w.y);
                    MMA_F16(acc[s][g * 2 + 1], af[s], w.z, w.w);
                }
        }
#pragma unroll
        for (int q = 0; q < 4; q++) wcur[q] = wnxt[q];
    }

    // ---- epilogue ----
    float bias[4][2];
#pragma unroll
    for (int n = 0; n < 4; n++) {
        int ob = wn * 32 + n * 8 + (lid & 3) * 2;
        bias[n][0] = __ldg(conv_b + ob);
        bias[n][1] = __ldg(conv_b + ob + 1);
    }
#pragma unroll
    for (int s = 0; s < 2; s++)
#pragma unroll
        for (int h = 0; h < 2; h++) {
            int m = m0 + wm * 32 + s * 16 + h * 8 + (lid >> 2);
            if (m < M_TOTAL) {
                float* op = out + (size_t)m * O_DIM + wn * 32 + (lid & 3) * 2;
#pragma unroll
                for (int n = 0; n < 4; n++) {
                    float2 v;
                    v.x = acc[s][n][h * 2 + 0] + bias[n][0];
                    v.y = acc[s][n][h * 2 + 1] + bias[n][1];
                    *(float2*)(op + n * 8) = v;
                }
            }
        }
}

// ---------------------------------------------------------------------------
extern "C" void kernel_launch(void* const* d_in, const int* in_sizes, int n_in,
                              void* d_out, int out_size) {
    const float* x       = (const float*)d_in[0];
    const void*  index   = d_in[1];
    const float* itp_mat = (const float*)d_in[2];
    const float* conv_w  = (const float*)d_in[3];
    const float* conv_b  = (const float*)d_in[4];
    float*       out     = (float*)d_out;

    prepack_wfrag_kernel<<<144, 256>>>(conv_w);
    detect_idx_kernel<<<64, 256>>>((const int*)index);
    interp_kernel<<<M_TOTAL / 8, 256>>>(x, index, itp_mat);
    gemm_mma_kernel<<<(M_TOTAL + BM - 1) / BM, 256>>>(conv_b, out);
}